// round 2
// baseline (speedup 1.0000x reference)
#include <cuda_runtime.h>
#include <cstdint>
#include <math_constants.h>

// ---------------------------------------------------------------------------
// Paged-cache block-diagonal causal attention (fill chunk), fused flash-attn.
// TF32 mma.sync path, fp32 I/O.
//
// Shapes: N_SEQS=8, Q_LEN=256, KV_LEN=2048, H=16, D=128.
// kv pos j of seq s:  j < 1792 -> k_cache[context_idx[s*2048+j]]
//                     j >= 1792 -> k[s*256 + (j-1792)]   (== scatter+gather)
// Mask: kv j visible to query i (within-seq) iff j <= i + 1792.
//
// context_idx dtype: JAX default (x64 disabled) downcasts the reference's
// int64 to int32. We read as int32, with a branchless probe that detects a
// genuine int64 layout (high words at odd positions all zero) just in case.
// ---------------------------------------------------------------------------

namespace {
constexpr int kNSeqs   = 8;
constexpr int kQLen    = 256;
constexpr int kKvLen   = 2048;
constexpr int kHeads   = 16;
constexpr int kHeadDim = 128;
constexpr int kCtxOld  = kKvLen - kQLen;   // 1792
constexpr int kOutCols = kHeads * kHeadDim; // 2048

constexpr int BM = 64;        // query tile
constexpr int BN = 64;        // kv tile
constexpr int kThreads = 128; // 4 warps, 16 query rows per warp

constexpr int KST = 132;      // smem row stride (floats) for Q/K/V tiles
constexpr int PST = 68;       // smem row stride for P

// 1/sqrt(128) * log2(e): fold into Q so softmax works in exp2 domain.
constexpr float kScaleLog2e = 0.08838834764831845f * 1.4426950408889634f;

constexpr int kQsOff = 0;
constexpr int kKsOff = kQsOff + BM * KST;
constexpr int kVsOff = kKsOff + BN * KST;
constexpr int kPsOff = kVsOff + BN * KST;
constexpr int kSmemFloats = kPsOff + 4 * 16 * PST;  // 29696 floats = 118784 B
}  // namespace

__device__ __forceinline__ uint32_t f2tf32(float f) {
    uint32_t u;
    asm("cvt.rna.tf32.f32 %0, %1;" : "=r"(u) : "f"(f));
    return u;
}

__device__ __forceinline__ void mma_tf32(float c[4], const uint32_t a[4],
                                         const uint32_t b[2]) {
    asm volatile(
        "mma.sync.aligned.m16n8k8.row.col.f32.tf32.tf32.f32 "
        "{%0,%1,%2,%3}, {%4,%5,%6,%7}, {%8,%9}, {%0,%1,%2,%3};"
        : "+f"(c[0]), "+f"(c[1]), "+f"(c[2]), "+f"(c[3])
        : "r"(a[0]), "r"(a[1]), "r"(a[2]), "r"(a[3]), "r"(b[0]), "r"(b[1]));
}

__global__ void __launch_bounds__(kThreads, 1)
fa_paged_kernel(const float* __restrict__ q, const float* __restrict__ kk,
                const float* __restrict__ vv, const float* __restrict__ k_cache,
                const float* __restrict__ v_cache,
                const int* __restrict__ ctx32, float* __restrict__ out) {
    extern __shared__ float smem[];
    float* Qs = smem + kQsOff;
    float* Ks = smem + kKsOff;
    float* Vs = smem + kVsOff;

    const int qt = blockIdx.x;   // 0..3  (query tile)
    const int h  = blockIdx.y;   // 0..15 (head)
    const int s  = blockIdx.z;   // 0..7  (seq)
    const int q0 = qt * BM;

    const int tid  = threadIdx.x;
    const int warp = tid >> 5;
    const int lane = tid & 31;
    const int g = lane >> 2;     // groupID (row within 8)
    const int t = lane & 3;      // threadID in group

    // dtype probe: if ctx is really int64 (LE), odd 32-bit words 1,3,5 are
    // high words of values < 2^15 -> all zero. An int32 permutation of
    // distinct values can have at most one zero among them.
    const bool ctx_is64 =
        (ctx32[1] == 0) && (ctx32[3] == 0) && (ctx32[5] == 0);

    // ---- load Q tile: pre-scale by 1/sqrt(D)*log2(e), round to tf32 ----
    {
        const int r     = tid >> 1;
        const int cbase = (tid & 1) * 64;
        const float* src =
            q + ((size_t)(s * kQLen + q0 + r) * kHeads + h) * kHeadDim;
        uint32_t* dst = (uint32_t*)(Qs + r * KST);
#pragma unroll
        for (int i = 0; i < 16; i++) {
            float4 f = *(const float4*)(src + cbase + i * 4);
            dst[cbase + i * 4 + 0] = f2tf32(f.x * kScaleLog2e);
            dst[cbase + i * 4 + 1] = f2tf32(f.y * kScaleLog2e);
            dst[cbase + i * 4 + 2] = f2tf32(f.z * kScaleLog2e);
            dst[cbase + i * 4 + 3] = f2tf32(f.w * kScaleLog2e);
        }
    }

    float oacc[16][4];
#pragma unroll
    for (int nb = 0; nb < 16; nb++)
        oacc[nb][0] = oacc[nb][1] = oacc[nb][2] = oacc[nb][3] = 0.f;
    float m1 = -CUDART_INF_F, m2 = -CUDART_INF_F;
    float l1 = 0.f, l2 = 0.f;

    const int qr0 = warp * 16;  // warp's first query row within tile
    // kv positions beyond q0+BM-1+1792 are invisible to every row -> skip.
    const int n_kv = min(kKvLen, q0 + BM - 1 + kCtxOld + 1);
    const int n_tiles = n_kv / BN;

    const uint32_t* Qsu = (const uint32_t*)Qs;
    const uint32_t* Ksu = (const uint32_t*)Ks;
    const uint32_t* Vsu = (const uint32_t*)Vs;
    uint32_t* Psu = (uint32_t*)(smem + kPsOff) + (warp * 16) * PST;

    for (int tile = 0; tile < n_tiles; tile++) {
        const int j0 = tile * BN;
        __syncthreads();  // previous tile's smem reads done

        // ---- gather K/V tile into smem (tf32-rounded) ----
        {
            const int jr    = tid >> 1;
            const int cbase = (tid & 1) * 64;
            const int j     = j0 + jr;
            const float *ksrc, *vsrc;
            if (j < kCtxOld) {
                const size_t ci = (size_t)s * kKvLen + j;
                const int slot =
                    ctx_is64 ? ctx32[2 * ci] : ctx32[ci];
                const size_t base = ((size_t)slot * kHeads + h) * kHeadDim;
                ksrc = k_cache + base;
                vsrc = v_cache + base;
            } else {
                const size_t base =
                    ((size_t)(s * kQLen + (j - kCtxOld)) * kHeads + h) * kHeadDim;
                ksrc = kk + base;
                vsrc = vv + base;
            }
            uint32_t* kd = (uint32_t*)(Ks + jr * KST);
            uint32_t* vd = (uint32_t*)(Vs + jr * KST);
#pragma unroll
            for (int i = 0; i < 16; i++) {
                float4 kf = *(const float4*)(ksrc + cbase + i * 4);
                float4 vf = *(const float4*)(vsrc + cbase + i * 4);
                kd[cbase + i * 4 + 0] = f2tf32(kf.x);
                kd[cbase + i * 4 + 1] = f2tf32(kf.y);
                kd[cbase + i * 4 + 2] = f2tf32(kf.z);
                kd[cbase + i * 4 + 3] = f2tf32(kf.w);
                vd[cbase + i * 4 + 0] = f2tf32(vf.x);
                vd[cbase + i * 4 + 1] = f2tf32(vf.y);
                vd[cbase + i * 4 + 2] = f2tf32(vf.z);
                vd[cbase + i * 4 + 3] = f2tf32(vf.w);
            }
        }
        __syncthreads();

        // ---- S = Q * K^T  (warp: 16 rows x 64 cols) ----
        float sacc[8][4];
#pragma unroll
        for (int nb = 0; nb < 8; nb++)
            sacc[nb][0] = sacc[nb][1] = sacc[nb][2] = sacc[nb][3] = 0.f;

#pragma unroll
        for (int kb = 0; kb < 16; kb++) {
            uint32_t a[4];
            const uint32_t* qrow = Qsu + (qr0 + g) * KST + kb * 8;
            a[0] = qrow[t];
            a[1] = qrow[8 * KST + t];
            a[2] = qrow[t + 4];
            a[3] = qrow[8 * KST + t + 4];
#pragma unroll
            for (int nb = 0; nb < 8; nb++) {
                uint32_t b[2];
                const uint32_t* krow = Ksu + (nb * 8 + g) * KST + kb * 8;
                b[0] = krow[t];
                b[1] = krow[t + 4];
                mma_tf32(sacc[nb], a, b);
            }
        }

        // ---- bottom-right causal mask (only the single boundary tile) ----
        if (j0 + BN - 1 > q0 + kCtxOld) {
            const int lim1 = q0 + qr0 + g + kCtxOld;  // row g visibility limit
            const int lim2 = lim1 + 8;                // row g+8
#pragma unroll
            for (int nb = 0; nb < 8; nb++) {
                const int c0 = j0 + nb * 8 + 2 * t;
                const int c1 = c0 + 1;
                if (c0 > lim1) sacc[nb][0] = -1e30f;
                if (c1 > lim1) sacc[nb][1] = -1e30f;
                if (c0 > lim2) sacc[nb][2] = -1e30f;
                if (c1 > lim2) sacc[nb][3] = -1e30f;
            }
        }

        // ---- online softmax (exp2 domain) ----
        float mx1 = fmaxf(sacc[0][0], sacc[0][1]);
        float mx2 = fmaxf(sacc[0][2], sacc[0][3]);
#pragma unroll
        for (int nb = 1; nb < 8; nb++) {
            mx1 = fmaxf(mx1, fmaxf(sacc[nb][0], sacc[nb][1]));
            mx2 = fmaxf(mx2, fmaxf(sacc[nb][2], sacc[nb][3]));
        }
        mx1 = fmaxf(mx1, __shfl_xor_sync(0xffffffffu, mx1, 1));
        mx1 = fmaxf(mx1, __shfl_xor_sync(0xffffffffu, mx1, 2));
        mx2 = fmaxf(mx2, __shfl_xor_sync(0xffffffffu, mx2, 1));
        mx2 = fmaxf(mx2, __shfl_xor_sync(0xffffffffu, mx2, 2));

        const float m1n = fmaxf(m1, mx1);
        const float m2n = fmaxf(m2, mx2);
        const float al1 = exp2f(m1 - m1n);
        const float al2 = exp2f(m2 - m2n);
        m1 = m1n;
        m2 = m2n;

        float sum1 = 0.f, sum2 = 0.f;
#pragma unroll
        for (int nb = 0; nb < 8; nb++) {
            const float p0 = exp2f(sacc[nb][0] - m1);
            const float p1 = exp2f(sacc[nb][1] - m1);
            const float p2 = exp2f(sacc[nb][2] - m2);
            const float p3 = exp2f(sacc[nb][3] - m2);
            sum1 += p0 + p1;
            sum2 += p2 + p3;
            uint32_t* pr = Psu + g * PST + nb * 8 + 2 * t;
            pr[0] = f2tf32(p0);
            pr[1] = f2tf32(p1);
            pr[8 * PST] = f2tf32(p2);
            pr[8 * PST + 1] = f2tf32(p3);
        }
        sum1 += __shfl_xor_sync(0xffffffffu, sum1, 1);
        sum1 += __shfl_xor_sync(0xffffffffu, sum1, 2);
        sum2 += __shfl_xor_sync(0xffffffffu, sum2, 1);
        sum2 += __shfl_xor_sync(0xffffffffu, sum2, 2);
        l1 = l1 * al1 + sum1;
        l2 = l2 * al2 + sum2;

#pragma unroll
        for (int nb = 0; nb < 16; nb++) {
            oacc[nb][0] *= al1;
            oacc[nb][1] *= al1;
            oacc[nb][2] *= al2;
            oacc[nb][3] *= al2;
        }
        __syncwarp();  // Ps written (per-warp private) -> visible to warp

        // ---- O += P * V  (warp: 16 rows x 128 dims) ----
#pragma unroll
        for (int kb = 0; kb < 8; kb++) {
            uint32_t a[4];
            const uint32_t* prow = Psu + g * PST + kb * 8;
            a[0] = prow[t];
            a[1] = prow[8 * PST + t];
            a[2] = prow[t + 4];
            a[3] = prow[8 * PST + t + 4];
#pragma unroll
            for (int nb = 0; nb < 16; nb++) {
                uint32_t b[2];
                const uint32_t* vrow = Vsu + (kb * 8 + t) * KST + nb * 8 + g;
                b[0] = vrow[0];
                b[1] = vrow[4 * KST];
                mma_tf32(oacc[nb], a, b);
            }
        }
    }

    // ---- epilogue: normalize and store ----
    const float inv1 = 1.f / l1;
    const float inv2 = 1.f / l2;
    const int row1 = s * kQLen + q0 + qr0 + g;
    float* o1 = out + (size_t)row1 * kOutCols + h * kHeadDim;
    float* o2 = o1 + (size_t)8 * kOutCols;
#pragma unroll
    for (int nb = 0; nb < 16; nb++) {
        const int c = nb * 8 + 2 * t;
        float2 w1 = make_float2(oacc[nb][0] * inv1, oacc[nb][1] * inv1);
        float2 w2 = make_float2(oacc[nb][2] * inv2, oacc[nb][3] * inv2);
        *(float2*)(o1 + c) = w1;
        *(float2*)(o2 + c) = w2;
    }
}

extern "C" void kernel_launch(void* const* d_in, const int* in_sizes, int n_in,
                              void* d_out, int out_size) {
    const float* q  = (const float*)d_in[0];
    const float* k  = (const float*)d_in[1];
    const float* v  = (const float*)d_in[2];
    const float* kc = (const float*)d_in[3];
    const float* vc = (const float*)d_in[4];
    // d_in[5] = allocated_idx (unused: allocated slots == ctx[:, -Q_LEN:])
    const int* ctx = (const int*)d_in[6];
    float* out = (float*)d_out;

    const int smem_bytes = kSmemFloats * (int)sizeof(float);
    cudaFuncSetAttribute(fa_paged_kernel,
                         cudaFuncAttributeMaxDynamicSharedMemorySize, smem_bytes);
    dim3 grid(kQLen / BM, kHeads, kNSeqs);
    fa_paged_kernel<<<grid, kThreads, smem_bytes>>>(q, k, v, kc, vc, ctx, out);
}